// round 1
// baseline (speedup 1.0000x reference)
#include <cuda_runtime.h>
#include <math.h>

#define T_STEPS 8192
#define HDIM    1024
#define G4      4096
#define NB      128
#define NT      512

// Scratch (sanctioned __device__ globals; no runtime allocation)
__device__ float        g_xg[(size_t)T_STEPS * G4];   // 128 MiB: per-t gate preactivations (input part + biases)
__device__ float        g_y0[(size_t)T_STEPS * HDIM]; // 32 MiB: layer-1 outputs
__device__ float        g_h[2][HDIM];                 // ping-pong hidden state
__device__ unsigned int g_count;                      // barrier counter (memset to 0 each launch)

__device__ __forceinline__ unsigned int ld_acquire_u32(const unsigned int* p) {
    unsigned int v;
    asm volatile("ld.acquire.gpu.global.u32 %0, [%1];" : "=r"(v) : "l"(p));
    return v;
}

// Grid-wide barrier for NB co-resident blocks. tgt is a running target kept in
// registers (identical sequence in every thread).
__device__ __forceinline__ void gbar(unsigned int& tgt) {
    tgt += NB;
    __syncthreads();
    if (threadIdx.x == 0) {
        atomicAdd(&g_count, 1u);
        while (ld_acquire_u32(&g_count) < tgt) { /* spin on L2 */ }
    }
    __syncthreads();
}

// Phase A/C: xg[t][row] = dot(W[row,:], src[t,:]) + bi[row] + bh[row]  for all t.
// Block b owns rows {g*1024 + b*8 + jj}; warp w owns k in [64w, 64w+64);
// lane = row index within block; weights live in registers.
__device__ void phase_inproj(const float* __restrict__ src,
                             const float* __restrict__ W,
                             const float* __restrict__ bi,
                             const float* __restrict__ bh,
                             float* __restrict__ sh,
                             float (*part)[17])
{
    const int tid  = threadIdx.x;
    const int w    = tid >> 5;
    const int lane = tid & 31;
    const int b    = blockIdx.x;
    const int row  = ((lane >> 3) << 10) + (b << 3) + (lane & 7);
    const int kb   = w << 6;

    float wreg[64];
    {
        const float4* Wp = reinterpret_cast<const float4*>(W + (size_t)row * HDIM + kb);
#pragma unroll
        for (int j = 0; j < 16; j++) {
            float4 v = Wp[j];
            wreg[4 * j + 0] = v.x; wreg[4 * j + 1] = v.y;
            wreg[4 * j + 2] = v.z; wreg[4 * j + 3] = v.w;
        }
    }
    float bias = 0.f;
    if (w == 0) bias = bi[row] + bh[row];

    // prefetched input chunk for current t
    float xv0 = src[kb + lane];
    float xv1 = src[kb + 32 + lane];

    for (int t = 0; t < T_STEPS; t++) {
        sh[kb + lane]      = xv0;
        sh[kb + 32 + lane] = xv1;
        __syncwarp();
        if (t + 1 < T_STEPS) {  // prefetch next t while FMAs run
            const float* s2 = src + (size_t)(t + 1) * HDIM;
            xv0 = s2[kb + lane];
            xv1 = s2[kb + 32 + lane];
        }
        float a0 = 0.f, a1 = 0.f, a2 = 0.f, a3 = 0.f;
#pragma unroll
        for (int j = 0; j < 16; j++) {
            float4 hv = *reinterpret_cast<const float4*>(sh + kb + 4 * j); // LDS.128 broadcast
            a0 = fmaf(wreg[4 * j + 0], hv.x, a0);
            a1 = fmaf(wreg[4 * j + 1], hv.y, a1);
            a2 = fmaf(wreg[4 * j + 2], hv.z, a2);
            a3 = fmaf(wreg[4 * j + 3], hv.w, a3);
        }
        part[lane][w] = (a0 + a1) + (a2 + a3);
        __syncthreads();
        if (w == 0) {
            float s = bias;
#pragma unroll
            for (int i = 0; i < 16; i++) s += part[lane][i];
            g_xg[(size_t)t * G4 + row] = s;   // block-private rows: no cross-SM coherence needed
        }
        __syncthreads();
    }
}

// Phase B/D: sequential scan. gates[row] = xg[t][row] + dot(Whh[row,:], h);
// one global barrier per step (ping-pong h makes single-sided sync safe).
template <int LAYER>
__device__ void phase_scan(const float* __restrict__ Whh,
                           float* __restrict__ out,
                           float* __restrict__ sh,
                           float (*part)[17],
                           unsigned int& tgt)
{
    const int tid   = threadIdx.x;
    const int w     = tid >> 5;
    const int lane  = tid & 31;
    const int b     = blockIdx.x;
    const int row   = ((lane >> 3) << 10) + (b << 3) + (lane & 7);
    const int kb    = w << 6;
    const int hbase = b << 3;

    float wreg[64];
    {
        const float4* Wp = reinterpret_cast<const float4*>(Whh + (size_t)row * HDIM + kb);
#pragma unroll
        for (int j = 0; j < 16; j++) {
            float4 v = Wp[j];
            wreg[4 * j + 0] = v.x; wreg[4 * j + 1] = v.y;
            wreg[4 * j + 2] = v.z; wreg[4 * j + 3] = v.w;
        }
    }

    // zero initial hidden state slice (buffer 0) and sync the grid
    if (w == 0 && lane < 8) g_h[0][hbase + lane] = 0.f;
    __threadfence();
    gbar(tgt);

    float c = 0.f;  // cell state: warp 0, lanes 0..7 of this block

    for (int t = 0; t < T_STEPS; t++) {
        const float* hr = g_h[t & 1];
        // L2-direct loads: ping-pong buffer lines from step t-2 may be stale in L1
        float h0 = __ldcg(hr + kb + lane);
        float h1 = __ldcg(hr + kb + 32 + lane);
        sh[kb + lane]      = h0;
        sh[kb + 32 + lane] = h1;
        __syncwarp();
        float a0 = 0.f, a1 = 0.f, a2 = 0.f, a3 = 0.f;
#pragma unroll
        for (int j = 0; j < 16; j++) {
            float4 hv = *reinterpret_cast<const float4*>(sh + kb + 4 * j);
            a0 = fmaf(wreg[4 * j + 0], hv.x, a0);
            a1 = fmaf(wreg[4 * j + 1], hv.y, a1);
            a2 = fmaf(wreg[4 * j + 2], hv.z, a2);
            a3 = fmaf(wreg[4 * j + 3], hv.w, a3);
        }
        part[lane][w] = (a0 + a1) + (a2 + a3);
        __syncthreads();
        if (w == 0) {
            float s = g_xg[(size_t)t * G4 + row];   // own block's writes: L1-coherent
#pragma unroll
            for (int i = 0; i < 16; i++) s += part[lane][i];
            // torch gate order: i, f, g, o; rows grouped by (gate, jj)
            float act = ((lane >> 3) == 2) ? tanhf(s) : 1.f / (1.f + expf(-s));
            const int jj = lane & 7;
            float gi = __shfl_sync(0xffffffffu, act, jj);
            float gf = __shfl_sync(0xffffffffu, act, 8 + jj);
            float gg = __shfl_sync(0xffffffffu, act, 16 + jj);
            float go = __shfl_sync(0xffffffffu, act, 24 + jj);
            if (lane < 8) {
                c = fmaf(gf, c, gi * gg);
                float hn = go * tanhf(c);
                g_h[(t + 1) & 1][hbase + lane] = hn;
                if (LAYER == 0) {
                    g_y0[(size_t)t * HDIM + hbase + lane] = hn;
                } else if (t == T_STEPS - 1) {
                    out[hbase + lane] = hn;
                }
            }
            __threadfence();   // warp-converged MEMBAR covers the predicated STGs above
        }
        gbar(tgt);
    }
}

__global__ void __launch_bounds__(NT, 1)
lstm_kernel(const float* __restrict__ x,
            const float* __restrict__ Wih0, const float* __restrict__ Whh0,
            const float* __restrict__ bi0,  const float* __restrict__ bh0,
            const float* __restrict__ Wih1, const float* __restrict__ Whh1,
            const float* __restrict__ bi1,  const float* __restrict__ bh1,
            float* __restrict__ out)
{
    __shared__ float sh[HDIM];
    __shared__ float part[32][17];   // [lane][warp], stride 17 -> conflict-free
    unsigned int tgt = 0;

    phase_inproj(x, Wih0, bi0, bh0, sh, part);          // xg0 (parallel over t)
    phase_scan<0>(Whh0, nullptr, sh, part, tgt);        // layer-1 recurrence -> y0
    phase_inproj(g_y0, Wih1, bi1, bh1, sh, part);       // xg1 (parallel over t)
    phase_scan<1>(Whh1, out, sh, part, tgt);            // layer-2 recurrence -> out
}

extern "C" void kernel_launch(void* const* d_in, const int* in_sizes, int n_in,
                              void* d_out, int out_size)
{
    const float* x    = (const float*)d_in[0];
    const float* Wih0 = (const float*)d_in[1];
    const float* Whh0 = (const float*)d_in[2];
    const float* bi0  = (const float*)d_in[3];
    const float* bh0  = (const float*)d_in[4];
    const float* Wih1 = (const float*)d_in[5];
    const float* Whh1 = (const float*)d_in[6];
    const float* bi1  = (const float*)d_in[7];
    const float* bh1  = (const float*)d_in[8];
    float* out = (float*)d_out;

    // Reset the barrier counter every launch so graph replays are deterministic.
    void* cptr = nullptr;
    cudaGetSymbolAddress(&cptr, g_count);
    cudaMemsetAsync(cptr, 0, sizeof(unsigned int));

    lstm_kernel<<<NB, NT>>>(x, Wih0, Whh0, bi0, bh0, Wih1, Whh1, bi1, bh1, out);
}

// round 2
// speedup vs baseline: 1.2031x; 1.2031x over previous
#include <cuda_runtime.h>
#include <math.h>

#define T_STEPS 8192
#define HDIM    1024
#define G4      4096
#define NB      128
#define NT      512

typedef unsigned long long u64;

// ── device-global scratch (no runtime allocation) ───────────────────────────
__device__ float    g_xg[(size_t)T_STEPS * G4];   // 128 MiB gate preactivations
__device__ float    g_y0[(size_t)T_STEPS * HDIM]; // 32 MiB layer-1 outputs
__device__ float    g_h[2][HDIM];                 // ping-pong hidden state
__device__ unsigned g_flag[NB * 32];              // per-block epoch, 128B stride
__device__ unsigned g_count;                      // barrier counter (memset/launch)

// ── primitives ──────────────────────────────────────────────────────────────
__device__ __forceinline__ unsigned ld_acq(const unsigned* p) {
    unsigned v;
    asm volatile("ld.acquire.gpu.global.u32 %0, [%1];" : "=r"(v) : "l"(p) : "memory");
    return v;
}
__device__ __forceinline__ void st_rel(unsigned* p, unsigned v) {
    asm volatile("st.release.gpu.global.u32 [%0], %1;" :: "l"(p), "r"(v) : "memory");
}
// packed dual FMA: d = a*b + d on two fp32 lanes (SASS FFMA2)
__device__ __forceinline__ void ffma2(u64& d, u64 a, u64 b) {
    asm volatile("fma.rn.f32x2 %0, %1, %2, %0;" : "+l"(d) : "l"(a), "l"(b));
}
__device__ __forceinline__ float red2(u64 a, u64 b) {
    float ax, ay, bx, by;
    asm("mov.b64 {%0,%1}, %2;" : "=f"(ax), "=f"(ay) : "l"(a));
    asm("mov.b64 {%0,%1}, %2;" : "=f"(bx), "=f"(by) : "l"(b));
    return (ax + ay) + (bx + by);
}
__device__ __forceinline__ float sig_fast(float x)  { return __fdividef(1.f, 1.f + __expf(-x)); }
__device__ __forceinline__ float tanh_fast(float x) { return __fdividef(2.f, 1.f + __expf(-2.f * x)) - 1.f; }

// grid barrier (used only 3× per launch: scan inits + inter-phase)
__device__ __forceinline__ void gbar(unsigned& tgt) {
    tgt += NB;
    __syncthreads();
    __threadfence();
    if (threadIdx.x == 0) {
        atomicAdd(&g_count, 1u);
        while (ld_acq(&g_count) < tgt) { }
    }
    __syncthreads();
}

// ── input projection: xg[t][row] = W·src[t] + bi + bh, 2-t tiled, f32x2 ─────
__device__ void phase_inproj(const float* __restrict__ src,
                             const float* __restrict__ W,
                             const float* __restrict__ bi,
                             const float* __restrict__ bh,
                             float (*shx)[HDIM],
                             float2 (*partV)[16][32])
{
    const int tid  = threadIdx.x;
    const int w    = tid >> 5;
    const int lane = tid & 31;
    const int b    = blockIdx.x;
    const int row  = ((lane >> 3) << 10) + (b << 3) + (lane & 7);
    const int kb   = w << 6;

    u64 w2[32];
    {
        const ulonglong2* Wp = reinterpret_cast<const ulonglong2*>(W + (size_t)row * HDIM + kb);
#pragma unroll
        for (int j = 0; j < 16; j++) { ulonglong2 v = Wp[j]; w2[2*j] = v.x; w2[2*j+1] = v.y; }
    }
    float bias = (w == 0) ? (bi[row] + bh[row]) : 0.f;

    float p00 = src[kb + lane],        p01 = src[kb + 32 + lane];
    float p10 = src[HDIM + kb + lane], p11 = src[HDIM + kb + 32 + lane];

    for (int tt = 0; tt < T_STEPS; tt += 2) {
        shx[0][kb + lane]      = p00;  shx[0][kb + 32 + lane] = p01;
        shx[1][kb + lane]      = p10;  shx[1][kb + 32 + lane] = p11;
        __syncwarp();
        if (tt + 2 < T_STEPS) {               // prefetch next 2 timesteps
            const float* s2 = src + (size_t)(tt + 2) * HDIM;
            p00 = s2[kb + lane];        p01 = s2[kb + 32 + lane];
            p10 = s2[HDIM + kb + lane]; p11 = s2[HDIM + kb + 32 + lane];
        }
        u64 a00 = 0, a01 = 0, a10 = 0, a11 = 0;
#pragma unroll
        for (int j = 0; j < 16; j++) {
            ulonglong2 h0 = *reinterpret_cast<const ulonglong2*>(&shx[0][kb + 4*j]);
            ulonglong2 h1 = *reinterpret_cast<const ulonglong2*>(&shx[1][kb + 4*j]);
            ffma2(a00, w2[2*j],   h0.x);  ffma2(a01, w2[2*j+1], h0.y);
            ffma2(a10, w2[2*j],   h1.x);  ffma2(a11, w2[2*j+1], h1.y);
        }
        const int p = (tt >> 1) & 1;          // parity double-buffer: 1 bar/iter
        partV[p][w][lane] = make_float2(red2(a00, a01), red2(a10, a11));
        __syncthreads();
        if (w == 0) {
            float sx = bias, sy = bias;
#pragma unroll
            for (int i = 0; i < 16; i++) { float2 v = partV[p][i][lane]; sx += v.x; sy += v.y; }
            g_xg[(size_t)tt * G4 + row]       = sx;
            g_xg[(size_t)(tt + 1) * G4 + row] = sy;
        }
    }
}

// ── recurrent scan: decentralized flag sync, 1 syncthreads/step ─────────────
template <int LAYER>
__device__ void phase_scan(const float* __restrict__ Whh,
                           float* __restrict__ out,
                           unsigned base,
                           float (*shx)[HDIM],
                           float (*partS)[16][32],
                           float* sh_h,
                           unsigned& tgt)
{
    const int tid   = threadIdx.x;
    const int w     = tid >> 5;
    const int lane  = tid & 31;
    const int b     = blockIdx.x;
    const int row   = ((lane >> 3) << 10) + (b << 3) + (lane & 7);
    const int kb    = w << 6;
    const int hbase = b << 3;

    u64 w2[32];
    {
        const ulonglong2* Wp = reinterpret_cast<const ulonglong2*>(Whh + (size_t)row * HDIM + kb);
#pragma unroll
        for (int j = 0; j < 16; j++) { ulonglong2 v = Wp[j]; w2[2*j] = v.x; w2[2*j+1] = v.y; }
    }

    // zero initial hidden slice (slot base&1 == 0 for both layers), grid-sync
    if (w == 0 && lane < 8) g_h[base & 1][hbase + lane] = 0.f;
    gbar(tgt);

    float c = 0.f;
    float xg_cur = 0.f;
    if (w == 0) xg_cur = __ldcg(&g_xg[row]);

    // warp w consumes h produced by blocks 8w..8w+7
    const unsigned* fp  = &g_flag[((unsigned)((w << 3) | (lane & 7))) * 32u];
    unsigned* myflag    = &g_flag[(unsigned)b * 32u];

    for (int t = 0; t < T_STEPS; t++) {
        const unsigned s = base + (unsigned)t;

        // wait for this chunk's 8 producers to publish h_in(s)
        for (;;) { unsigned v = ld_acq(fp); if (__all_sync(0xffffffffu, v >= s)) break; }

        const float* hr = g_h[s & 1];
        float h0 = __ldcg(hr + kb + lane);
        float h1 = __ldcg(hr + kb + 32 + lane);
        shx[0][kb + lane]      = h0;
        shx[0][kb + 32 + lane] = h1;
        __syncwarp();

        u64 a0 = 0, a1 = 0, a2 = 0, a3 = 0;
#pragma unroll
        for (int j = 0; j < 16; j++) {
            ulonglong2 hv = *reinterpret_cast<const ulonglong2*>(&shx[0][kb + 4*j]);
            if (j & 1) { ffma2(a2, w2[2*j], hv.x); ffma2(a3, w2[2*j+1], hv.y); }
            else       { ffma2(a0, w2[2*j], hv.x); ffma2(a1, w2[2*j+1], hv.y); }
        }
        const int p = t & 1;                  // parity double-buffer: 1 bar/step
        partS[p][w][lane] = red2(a0, a1) + red2(a2, a3);
        __syncthreads();

        if (w == 0) {
            // prefetch next xg early (DRAM-latency hiding)
            float xnext = (t + 1 < T_STEPS) ? __ldcg(&g_xg[(size_t)(t + 1) * G4 + row]) : 0.f;
            float sg = xg_cur;
#pragma unroll
            for (int i = 0; i < 16; i++) sg += partS[p][i][lane];

            // torch gate order: i, f, g, o  (lane>>3 selects gate group)
            float act = ((lane >> 3) == 2) ? tanh_fast(sg) : sig_fast(sg);
            const int jj = lane & 7;
            float gi = __shfl_sync(0xffffffffu, act, jj);
            float gf = __shfl_sync(0xffffffffu, act, 8 + jj);
            float gg = __shfl_sync(0xffffffffu, act, 16 + jj);
            float go = __shfl_sync(0xffffffffu, act, 24 + jj);
            float hn = 0.f;
            if (lane < 8) {
                c  = fmaf(gf, c, gi * gg);
                hn = go * tanh_fast(c);
                sh_h[lane] = hn;
            }
            __syncwarp();
            if (lane == 0) {
                // single-thread publish: 2×STG.128 then release flag (no membar)
                float4 v0 = *reinterpret_cast<const float4*>(&sh_h[0]);
                float4 v1 = *reinterpret_cast<const float4*>(&sh_h[4]);
                float* hw = &g_h[(s + 1) & 1][hbase];
                reinterpret_cast<float4*>(hw)[0] = v0;
                reinterpret_cast<float4*>(hw)[1] = v1;
                st_rel(myflag, s + 1u);
            }
            if (LAYER == 0) {
                if (lane < 8) g_y0[(size_t)t * HDIM + hbase + lane] = hn;
            } else {
                if (t == T_STEPS - 1 && lane < 8) out[hbase + lane] = hn;
            }
            xg_cur = xnext;
        }
    }
}

// ── kernel ──────────────────────────────────────────────────────────────────
__global__ void __launch_bounds__(NT, 1)
lstm_kernel(const float* __restrict__ x,
            const float* __restrict__ Wih0, const float* __restrict__ Whh0,
            const float* __restrict__ bi0,  const float* __restrict__ bh0,
            const float* __restrict__ Wih1, const float* __restrict__ Whh1,
            const float* __restrict__ bi1,  const float* __restrict__ bh1,
            float* __restrict__ out)
{
    __shared__ float  shx[2][HDIM];
    __shared__ float  partS[2][16][32];
    __shared__ float2 partV[2][16][32];
    __shared__ alignas(16) float sh_h[8];
    unsigned tgt = 0;

    phase_inproj(x, Wih0, bi0, bh0, shx, partV);                 // xg layer 0
    phase_scan<0>(Whh0, nullptr, 0u, shx, partS, sh_h, tgt);     // scan layer 0
    gbar(tgt);                                                   // publish y0
    phase_inproj(g_y0, Wih1, bi1, bh1, shx, partV);              // xg layer 1
    phase_scan<1>(Whh1, out, (unsigned)T_STEPS, shx, partS, sh_h, tgt); // scan layer 1
}

extern "C" void kernel_launch(void* const* d_in, const int* in_sizes, int n_in,
                              void* d_out, int out_size)
{
    const float* x    = (const float*)d_in[0];
    const float* Wih0 = (const float*)d_in[1];
    const float* Whh0 = (const float*)d_in[2];
    const float* bi0  = (const float*)d_in[3];
    const float* bh0  = (const float*)d_in[4];
    const float* Wih1 = (const float*)d_in[5];
    const float* Whh1 = (const float*)d_in[6];
    const float* bi1  = (const float*)d_in[7];
    const float* bh1  = (const float*)d_in[8];
    float* out = (float*)d_out;

    // reset flags + barrier counter so graph replays are deterministic
    void* fptr = nullptr; cudaGetSymbolAddress(&fptr, g_flag);
    cudaMemsetAsync(fptr, 0, NB * 32 * sizeof(unsigned));
    void* cptr = nullptr; cudaGetSymbolAddress(&cptr, g_count);
    cudaMemsetAsync(cptr, 0, sizeof(unsigned));

    lstm_kernel<<<NB, NT>>>(x, Wih0, Whh0, bi0, bh0, Wih1, Whh1, bi1, bh1, out);
}

// round 3
// speedup vs baseline: 2.1286x; 1.7692x over previous
#include <cuda_runtime.h>
#include <math.h>

#define T_STEPS 8192
#define HDIM    1024
#define G4      4096
#define NB      128
#define NT      512

typedef unsigned long long u64;

// ── device-global scratch (no runtime allocation) ───────────────────────────
__device__ float    g_xg[(size_t)T_STEPS * G4];   // 128 MiB gate preactivations
__device__ float    g_y0[(size_t)T_STEPS * HDIM]; // 32 MiB layer-1 outputs
__device__ u64      g_hp[2][HDIM];                // ping-pong {tag:u32 hi, h:f32 lo} pairs
__device__ unsigned g_count;                      // barrier counter (memset/launch)

// ── primitives ──────────────────────────────────────────────────────────────
__device__ __forceinline__ unsigned ld_acq(const unsigned* p) {
    unsigned v;
    asm volatile("ld.acquire.gpu.global.u32 %0, [%1];" : "=r"(v) : "l"(p) : "memory");
    return v;
}
__device__ __forceinline__ u64 ld_strong64(const u64* p) {
    u64 v;
    asm volatile("ld.relaxed.gpu.global.b64 %0, [%1];" : "=l"(v) : "l"(p) : "memory");
    return v;
}
__device__ __forceinline__ void st_strong64(u64* p, u64 v) {
    asm volatile("st.relaxed.gpu.global.b64 [%0], %1;" :: "l"(p), "l"(v) : "memory");
}
// packed dual FMA: d = a*b + d on two fp32 lanes (SASS FFMA2)
__device__ __forceinline__ void ffma2(u64& d, u64 a, u64 b) {
    asm volatile("fma.rn.f32x2 %0, %1, %2, %0;" : "+l"(d) : "l"(a), "l"(b));
}
__device__ __forceinline__ float red2(u64 a, u64 b) {
    float ax, ay, bx, by;
    asm("mov.b64 {%0,%1}, %2;" : "=f"(ax), "=f"(ay) : "l"(a));
    asm("mov.b64 {%0,%1}, %2;" : "=f"(bx), "=f"(by) : "l"(b));
    return (ax + ay) + (bx + by);
}
__device__ __forceinline__ float sig_fast(float x)  { return __fdividef(1.f, 1.f + __expf(-x)); }
__device__ __forceinline__ float tanh_fast(float x) { return __fdividef(2.f, 1.f + __expf(-2.f * x)) - 1.f; }

// grid barrier (used only 3× per launch)
__device__ __forceinline__ void gbar(unsigned& tgt) {
    tgt += NB;
    __syncthreads();
    __threadfence();
    if (threadIdx.x == 0) {
        atomicAdd(&g_count, 1u);
        while (ld_acq(&g_count) < tgt) { }
    }
    __syncthreads();
}

// ── input projection: xg[t][row] = W·src[t] + bi + bh, 2-t tiled, f32x2 ─────
__device__ void phase_inproj(const float* __restrict__ src,
                             const float* __restrict__ W,
                             const float* __restrict__ bi,
                             const float* __restrict__ bh,
                             float (*shx)[HDIM],
                             float2 (*partV)[16][32])
{
    const int tid  = threadIdx.x;
    const int w    = tid >> 5;
    const int lane = tid & 31;
    const int b    = blockIdx.x;
    const int row  = ((lane >> 3) << 10) + (b << 3) + (lane & 7);
    const int kb   = w << 6;

    u64 w2[32];
    {
        const ulonglong2* Wp = reinterpret_cast<const ulonglong2*>(W + (size_t)row * HDIM + kb);
#pragma unroll
        for (int j = 0; j < 16; j++) { ulonglong2 v = Wp[j]; w2[2*j] = v.x; w2[2*j+1] = v.y; }
    }
    float bias = (w == 0) ? (bi[row] + bh[row]) : 0.f;

    float p00 = src[kb + lane],        p01 = src[kb + 32 + lane];
    float p10 = src[HDIM + kb + lane], p11 = src[HDIM + kb + 32 + lane];

    for (int tt = 0; tt < T_STEPS; tt += 2) {
        shx[0][kb + lane]      = p00;  shx[0][kb + 32 + lane] = p01;
        shx[1][kb + lane]      = p10;  shx[1][kb + 32 + lane] = p11;
        __syncwarp();
        if (tt + 2 < T_STEPS) {               // prefetch next 2 timesteps
            const float* s2 = src + (size_t)(tt + 2) * HDIM;
            p00 = s2[kb + lane];        p01 = s2[kb + 32 + lane];
            p10 = s2[HDIM + kb + lane]; p11 = s2[HDIM + kb + 32 + lane];
        }
        u64 a00 = 0, a01 = 0, a10 = 0, a11 = 0;
#pragma unroll
        for (int j = 0; j < 16; j++) {
            ulonglong2 h0 = *reinterpret_cast<const ulonglong2*>(&shx[0][kb + 4*j]);
            ulonglong2 h1 = *reinterpret_cast<const ulonglong2*>(&shx[1][kb + 4*j]);
            ffma2(a00, w2[2*j],   h0.x);  ffma2(a01, w2[2*j+1], h0.y);
            ffma2(a10, w2[2*j],   h1.x);  ffma2(a11, w2[2*j+1], h1.y);
        }
        const int p = (tt >> 1) & 1;          // parity double-buffer: 1 bar/iter
        partV[p][w][lane] = make_float2(red2(a00, a01), red2(a10, a11));
        __syncthreads();
        if (w == 0) {
            float sx = bias, sy = bias;
#pragma unroll
            for (int i = 0; i < 16; i++) { float2 v = partV[p][i][lane]; sx += v.x; sy += v.y; }
            g_xg[(size_t)tt * G4 + row]       = sx;
            g_xg[(size_t)(tt + 1) * G4 + row] = sy;
        }
    }
}

// ── recurrent scan: tagged {epoch,h} pairs — poll IS the data fetch ─────────
template <int LAYER>
__device__ void phase_scan(const float* __restrict__ Whh,
                           float* __restrict__ out,
                           unsigned base,
                           float (*shx)[HDIM],
                           float (*partS)[16][32],
                           unsigned& tgt)
{
    const int tid   = threadIdx.x;
    const int w     = tid >> 5;
    const int lane  = tid & 31;
    const int b     = blockIdx.x;
    const int row   = ((lane >> 3) << 10) + (b << 3) + (lane & 7);
    const int kb    = w << 6;
    const int hbase = b << 3;

    u64 w2[32];
    {
        const ulonglong2* Wp = reinterpret_cast<const ulonglong2*>(Whh + (size_t)row * HDIM + kb);
#pragma unroll
        for (int j = 0; j < 16; j++) { ulonglong2 v = Wp[j]; w2[2*j] = v.x; w2[2*j+1] = v.y; }
    }

    // init own h pairs: {tag=base, h=0} in slot base&1, then grid-sync
    if (w == 0 && lane < 8)
        st_strong64(&g_hp[base & 1][hbase + lane], ((u64)base << 32));
    gbar(tgt);

    float c = 0.f;
    float xg_cur = 0.f;
    if (w == 0) xg_cur = __ldcg(&g_xg[row]);

    for (int t = 0; t < T_STEPS; t++) {
        const unsigned s = base + (unsigned)t;

        // poll this warp's 64-value chunk; tag match == data valid (8B atomicity)
        const u64* hp = &g_hp[s & 1][kb];
        u64 v0, v1;
        int miss = 0;
        for (;;) {
            v0 = ld_strong64(hp + lane);
            v1 = ld_strong64(hp + 32 + lane);
            bool ok = ((unsigned)(v0 >> 32) == s) & ((unsigned)(v1 >> 32) == s);
            if (__all_sync(0xffffffffu, ok)) break;
            if (++miss > 4) __nanosleep(40);
        }
        shx[0][kb + lane]      = __uint_as_float((unsigned)v0);
        shx[0][kb + 32 + lane] = __uint_as_float((unsigned)v1);
        __syncwarp();

        u64 a0 = 0, a1 = 0, a2 = 0, a3 = 0;
#pragma unroll
        for (int j = 0; j < 16; j++) {
            ulonglong2 hv = *reinterpret_cast<const ulonglong2*>(&shx[0][kb + 4*j]);
            if (j & 1) { ffma2(a2, w2[2*j], hv.x); ffma2(a3, w2[2*j+1], hv.y); }
            else       { ffma2(a0, w2[2*j], hv.x); ffma2(a1, w2[2*j+1], hv.y); }
        }
        const int p = t & 1;                  // parity double-buffer: 1 bar/step
        partS[p][w][lane] = red2(a0, a1) + red2(a2, a3);
        __syncthreads();

        if (w == 0) {
            float xnext = (t + 1 < T_STEPS) ? __ldcg(&g_xg[(size_t)(t + 1) * G4 + row]) : 0.f;
            float sg = xg_cur;
#pragma unroll
            for (int i = 0; i < 16; i++) sg += partS[p][i][lane];

            // torch gate order: i, f, g, o  (lane>>3 selects gate group)
            float act = ((lane >> 3) == 2) ? tanh_fast(sg) : sig_fast(sg);
            const int jj = lane & 7;
            float gi = __shfl_sync(0xffffffffu, act, jj);
            float gf = __shfl_sync(0xffffffffu, act, 8 + jj);
            float gg = __shfl_sync(0xffffffffu, act, 16 + jj);
            float go = __shfl_sync(0xffffffffu, act, 24 + jj);
            if (lane < 8) {
                c = fmaf(gf, c, gi * gg);
                float hn = go * tanh_fast(c);
                // publish: single predicated STG.64 — tag and value in one atom
                u64 pk = ((u64)(s + 1) << 32) | (u64)__float_as_uint(hn);
                st_strong64(&g_hp[(s + 1) & 1][hbase + lane], pk);
                if (LAYER == 0) {
                    g_y0[(size_t)t * HDIM + hbase + lane] = hn;
                } else if (t == T_STEPS - 1) {
                    out[hbase + lane] = hn;
                }
            }
            xg_cur = xnext;
        }
    }
}

// ── kernel ──────────────────────────────────────────────────────────────────
__global__ void __launch_bounds__(NT, 1)
lstm_kernel(const float* __restrict__ x,
            const float* __restrict__ Wih0, const float* __restrict__ Whh0,
            const float* __restrict__ bi0,  const float* __restrict__ bh0,
            const float* __restrict__ Wih1, const float* __restrict__ Whh1,
            const float* __restrict__ bi1,  const float* __restrict__ bh1,
            float* __restrict__ out)
{
    __shared__ float  shx[2][HDIM];
    __shared__ float  partS[2][16][32];
    __shared__ float2 partV[2][16][32];
    unsigned tgt = 0;

    phase_inproj(x, Wih0, bi0, bh0, shx, partV);                 // xg layer 0
    phase_scan<0>(Whh0, nullptr, 0u, shx, partS, tgt);           // scan layer 0
    gbar(tgt);                                                   // publish y0
    phase_inproj(g_y0, Wih1, bi1, bh1, shx, partV);              // xg layer 1
    phase_scan<1>(Whh1, out, (unsigned)T_STEPS, shx, partS, tgt);// scan layer 1
}

extern "C" void kernel_launch(void* const* d_in, const int* in_sizes, int n_in,
                              void* d_out, int out_size)
{
    const float* x    = (const float*)d_in[0];
    const float* Wih0 = (const float*)d_in[1];
    const float* Whh0 = (const float*)d_in[2];
    const float* bi0  = (const float*)d_in[3];
    const float* bh0  = (const float*)d_in[4];
    const float* Wih1 = (const float*)d_in[5];
    const float* Whh1 = (const float*)d_in[6];
    const float* bi1  = (const float*)d_in[7];
    const float* bh1  = (const float*)d_in[8];
    float* out = (float*)d_out;

    // reset pair tags + barrier counter so graph replays are deterministic
    void* hptr = nullptr; cudaGetSymbolAddress(&hptr, g_hp);
    cudaMemsetAsync(hptr, 0, 2 * HDIM * sizeof(u64));
    void* cptr = nullptr; cudaGetSymbolAddress(&cptr, g_count);
    cudaMemsetAsync(cptr, 0, sizeof(unsigned));

    lstm_kernel<<<NB, NT>>>(x, Wih0, Whh0, bi0, bh0, Wih1, Whh1, bi1, bh1, out);
}

// round 4
// speedup vs baseline: 2.1610x; 1.0152x over previous
#include <cuda_runtime.h>
#include <math.h>

#define T_STEPS 8192
#define HDIM    1024
#define G4      4096
#define NB      128
#define NT      512

typedef unsigned long long u64;

// ── device-global scratch (no runtime allocation) ───────────────────────────
__device__ float    g_xg[(size_t)T_STEPS * G4];   // 128 MiB gate preactivations
__device__ float    g_y0[(size_t)T_STEPS * HDIM]; // 32 MiB layer-1 outputs
__device__ u64      g_hp[2][HDIM];                // ping-pong {tag:u32 hi, h:f32 lo} pairs
__device__ unsigned g_count;                      // barrier counter (memset/launch)

// ── primitives ──────────────────────────────────────────────────────────────
__device__ __forceinline__ unsigned ld_acq(const unsigned* p) {
    unsigned v;
    asm volatile("ld.acquire.gpu.global.u32 %0, [%1];" : "=r"(v) : "l"(p) : "memory");
    return v;
}
__device__ __forceinline__ void st_strong64(u64* p, u64 v) {
    asm volatile("st.relaxed.gpu.global.b64 [%0], %1;" :: "l"(p), "l"(v) : "memory");
}
// packed dual FMA: d = a*b + d on two fp32 lanes (SASS FFMA2)
__device__ __forceinline__ void ffma2(u64& d, u64 a, u64 b) {
    asm volatile("fma.rn.f32x2 %0, %1, %2, %0;" : "+l"(d) : "l"(a), "l"(b));
}
__device__ __forceinline__ float red2(u64 a, u64 b) {
    float ax, ay, bx, by;
    asm("mov.b64 {%0,%1}, %2;" : "=f"(ax), "=f"(ay) : "l"(a));
    asm("mov.b64 {%0,%1}, %2;" : "=f"(bx), "=f"(by) : "l"(b));
    return (ax + ay) + (bx + by);
}
__device__ __forceinline__ float sig_fast(float x)  { return __fdividef(1.f, 1.f + __expf(-x)); }
__device__ __forceinline__ float tanh_fast(float x) { return __fdividef(2.f, 1.f + __expf(-2.f * x)) - 1.f; }

// grid barrier (used only 3× per launch)
__device__ __forceinline__ void gbar(unsigned& tgt) {
    tgt += NB;
    __syncthreads();
    __threadfence();
    if (threadIdx.x == 0) {
        atomicAdd(&g_count, 1u);
        while (ld_acq(&g_count) < tgt) { }
    }
    __syncthreads();
}

// ── input projection: xg[t][row] = W·src[t] + bi + bh, 2-t tiled, f32x2 ─────
__device__ void phase_inproj(const float* __restrict__ src,
                             const float* __restrict__ W,
                             const float* __restrict__ bi,
                             const float* __restrict__ bh,
                             float (*shx)[HDIM],
                             float2 (*partV)[16][32])
{
    const int tid  = threadIdx.x;
    const int w    = tid >> 5;
    const int lane = tid & 31;
    const int b    = blockIdx.x;
    const int row  = ((lane >> 3) << 10) + (b << 3) + (lane & 7);
    const int kb   = w << 6;

    u64 w2[32];
    {
        const ulonglong2* Wp = reinterpret_cast<const ulonglong2*>(W + (size_t)row * HDIM + kb);
#pragma unroll
        for (int j = 0; j < 16; j++) { ulonglong2 v = Wp[j]; w2[2*j] = v.x; w2[2*j+1] = v.y; }
    }
    float bias = (w == 0) ? (bi[row] + bh[row]) : 0.f;

    float p00 = src[kb + lane],        p01 = src[kb + 32 + lane];
    float p10 = src[HDIM + kb + lane], p11 = src[HDIM + kb + 32 + lane];

    for (int tt = 0; tt < T_STEPS; tt += 2) {
        shx[0][kb + lane]      = p00;  shx[0][kb + 32 + lane] = p01;
        shx[1][kb + lane]      = p10;  shx[1][kb + 32 + lane] = p11;
        __syncwarp();
        if (tt + 2 < T_STEPS) {               // prefetch next 2 timesteps
            const float* s2 = src + (size_t)(tt + 2) * HDIM;
            p00 = s2[kb + lane];        p01 = s2[kb + 32 + lane];
            p10 = s2[HDIM + kb + lane]; p11 = s2[HDIM + kb + 32 + lane];
        }
        u64 a00 = 0, a01 = 0, a10 = 0, a11 = 0;
#pragma unroll
        for (int j = 0; j < 16; j++) {
            ulonglong2 h0 = *reinterpret_cast<const ulonglong2*>(&shx[0][kb + 4*j]);
            ulonglong2 h1 = *reinterpret_cast<const ulonglong2*>(&shx[1][kb + 4*j]);
            ffma2(a00, w2[2*j],   h0.x);  ffma2(a01, w2[2*j+1], h0.y);
            ffma2(a10, w2[2*j],   h1.x);  ffma2(a11, w2[2*j+1], h1.y);
        }
        const int p = (tt >> 1) & 1;          // parity double-buffer: 1 bar/iter
        partV[p][w][lane] = make_float2(red2(a00, a01), red2(a10, a11));
        __syncthreads();
        if (w == 0) {
            float sx = bias, sy = bias;
#pragma unroll
            for (int i = 0; i < 16; i++) { float2 v = partV[p][i][lane]; sx += v.x; sy += v.y; }
            g_xg[(size_t)tt * G4 + row]       = sx;
            g_xg[(size_t)(tt + 1) * G4 + row] = sy;
        }
    }
}

// ── recurrent scan: tagged {epoch,h} pairs, vector poll, tree reduce ────────
template <int LAYER>
__device__ void phase_scan(const float* __restrict__ Whh,
                           float* __restrict__ out,
                           unsigned base,
                           float (*shx)[HDIM],
                           float (*partS)[16][32],
                           unsigned& tgt)
{
    const int tid   = threadIdx.x;
    const int w     = tid >> 5;
    const int lane  = tid & 31;
    const int b     = blockIdx.x;
    const int row   = ((lane >> 3) << 10) + (b << 3) + (lane & 7);
    const int kb    = w << 6;
    const int hbase = b << 3;

    u64 w2[32];
    {
        const ulonglong2* Wp = reinterpret_cast<const ulonglong2*>(Whh + (size_t)row * HDIM + kb);
#pragma unroll
        for (int j = 0; j < 16; j++) { ulonglong2 v = Wp[j]; w2[2*j] = v.x; w2[2*j+1] = v.y; }
    }

    // init own h pairs: {tag=base, h=0} in slot base&1, then grid-sync
    if (w == 0 && lane < 8)
        st_strong64(&g_hp[base & 1][hbase + lane], ((u64)base << 32));
    gbar(tgt);

    float c = 0.f;
    float xg_cur = 0.f;
    if (w == 0) xg_cur = __ldcg(&g_xg[row]);

    for (int t = 0; t < T_STEPS; t++) {
        const unsigned s = base + (unsigned)t;

        // vector poll: one LDG.128 covers 2 tagged pairs; tag match == valid
        const ulonglong2* hp = reinterpret_cast<const ulonglong2*>(&g_hp[s & 1][kb]) + lane;
        ulonglong2 v;
        int miss = 0;
        for (;;) {
            v = __ldcv(hp);
            bool ok = ((unsigned)(v.x >> 32) == s) & ((unsigned)(v.y >> 32) == s);
            if (__all_sync(0xffffffffu, ok)) break;
            if (++miss > 64) __nanosleep(20);
        }
        // stage: one STS.64 per lane
        *reinterpret_cast<float2*>(&shx[0][kb + 2 * lane]) =
            make_float2(__uint_as_float((unsigned)v.x), __uint_as_float((unsigned)v.y));
        __syncwarp();

        u64 a0 = 0, a1 = 0, a2 = 0, a3 = 0;
#pragma unroll
        for (int j = 0; j < 16; j++) {
            ulonglong2 hv = *reinterpret_cast<const ulonglong2*>(&shx[0][kb + 4*j]);
            if (j & 1) { ffma2(a2, w2[2*j], hv.x); ffma2(a3, w2[2*j+1], hv.y); }
            else       { ffma2(a0, w2[2*j], hv.x); ffma2(a1, w2[2*j+1], hv.y); }
        }
        const int p = t & 1;                  // parity double-buffer: 1 bar/step
        float partial = red2(a0, a1) + red2(a2, a3);
        if (w == 0) partial += xg_cur;        // fold xg into own partial pre-store
        partS[p][w][lane] = partial;
        __syncthreads();

        if (w == 0) {
            float xnext = (t + 1 < T_STEPS) ? __ldcg(&g_xg[(size_t)(t + 1) * G4 + row]) : 0.f;
            // tree reduce: issue all 16 LDS upfront, depth-4 add tree
            float r[16];
#pragma unroll
            for (int i = 0; i < 16; i++) r[i] = partS[p][i][lane];
#pragma unroll
            for (int i = 0; i < 8; i++) r[i] = r[2*i] + r[2*i+1];
#pragma unroll
            for (int i = 0; i < 4; i++) r[i] = r[2*i] + r[2*i+1];
            float sg = (r[0] + r[1]) + (r[2] + r[3]);

            // torch gate order: i, f, g, o  (lane>>3 selects gate group)
            float act = ((lane >> 3) == 2) ? tanh_fast(sg) : sig_fast(sg);
            const int jj = lane & 7;
            float gi = __shfl_sync(0xffffffffu, act, jj);
            float gf = __shfl_sync(0xffffffffu, act, 8 + jj);
            float gg = __shfl_sync(0xffffffffu, act, 16 + jj);
            float go = __shfl_sync(0xffffffffu, act, 24 + jj);
            if (lane < 8) {
                c = fmaf(gf, c, gi * gg);
                float hn = go * tanh_fast(c);
                // publish first: single predicated STG.64 — tag + value one atom
                u64 pk = ((u64)(s + 1) << 32) | (u64)__float_as_uint(hn);
                st_strong64(&g_hp[(s + 1) & 1][hbase + lane], pk);
                if (LAYER == 0) {
                    g_y0[(size_t)t * HDIM + hbase + lane] = hn;
                } else if (t == T_STEPS - 1) {
                    out[hbase + lane] = hn;
                }
            }
            xg_cur = xnext;
        }
    }
}

// ── kernel ──────────────────────────────────────────────────────────────────
__global__ void __launch_bounds__(NT, 1)
lstm_kernel(const float* __restrict__ x,
            const float* __restrict__ Wih0, const float* __restrict__ Whh0,
            const float* __restrict__ bi0,  const float* __restrict__ bh0,
            const float* __restrict__ Wih1, const float* __restrict__ Whh1,
            const float* __restrict__ bi1,  const float* __restrict__ bh1,
            float* __restrict__ out)
{
    __shared__ float  shx[2][HDIM];
    __shared__ float  partS[2][16][32];
    __shared__ float2 partV[2][16][32];
    unsigned tgt = 0;

    phase_inproj(x, Wih0, bi0, bh0, shx, partV);                 // xg layer 0
    phase_scan<0>(Whh0, nullptr, 0u, shx, partS, tgt);           // scan layer 0
    gbar(tgt);                                                   // publish y0
    phase_inproj(g_y0, Wih1, bi1, bh1, shx, partV);              // xg layer 1
    phase_scan<1>(Whh1, out, (unsigned)T_STEPS, shx, partS, tgt);// scan layer 1
}

extern "C" void kernel_launch(void* const* d_in, const int* in_sizes, int n_in,
                              void* d_out, int out_size)
{
    const float* x    = (const float*)d_in[0];
    const float* Wih0 = (const float*)d_in[1];
    const float* Whh0 = (const float*)d_in[2];
    const float* bi0  = (const float*)d_in[3];
    const float* bh0  = (const float*)d_in[4];
    const float* Wih1 = (const float*)d_in[5];
    const float* Whh1 = (const float*)d_in[6];
    const float* bi1  = (const float*)d_in[7];
    const float* bh1  = (const float*)d_in[8];
    float* out = (float*)d_out;

    // reset pair tags + barrier counter so graph replays are deterministic
    void* hptr = nullptr; cudaGetSymbolAddress(&hptr, g_hp);
    cudaMemsetAsync(hptr, 0, 2 * HDIM * sizeof(u64));
    void* cptr = nullptr; cudaGetSymbolAddress(&cptr, g_count);
    cudaMemsetAsync(cptr, 0, sizeof(unsigned));

    lstm_kernel<<<NB, NT>>>(x, Wih0, Whh0, bi0, bh0, Wih1, Whh1, bi1, bh1, out);
}